// round 1
// baseline (speedup 1.0000x reference)
#include <cuda_runtime.h>
#include <cstdint>

// BrainSphereCNN: 16-layer gather->GEMM->BN(train)->ReLU stack.
// N=40962 nodes, 7 neighbors/node. Middle layers: [N,896]@[896,128].
// Strategy: fp32 GEMM using packed fma.rn.f32x2 (2x FFMA throughput on sm_103a),
// BN affine + ReLU of the PREVIOUS layer fused into the gather of the next GEMM,
// deterministic two-level BN statistics reduction.

#define NN    40962
#define C     128
#define NB0   641   // ceil(NN/64)
#define NBM   321   // ceil(NN/128)
#define NCLS  36
#define EPSBN 1e-5f

// Scratch (static device globals -- no allocation in kernel_launch)
__device__ float g_Y[2ull * NN * C];     // ping-pong activation buffers (pre-BN linear outputs)
__device__ float g_psum[NB0 * C];        // per-block partial channel sums
__device__ float g_psq[NB0 * C];         // per-block partial channel sums of squares
__device__ float g_scale[C];             // BN affine: scale = g * rsqrt(var+eps)
__device__ float g_shift[C];             // BN affine: shift = beta - mu*scale

// ---- packed fp32x2 helpers --------------------------------------------------
#define FMA2(d, a, b) \
    asm("fma.rn.f32x2 %0, %1, %2, %0;" : "+l"(d) : "l"(a), "l"(b))

#define PACK2(d, lo, hi) \
    asm("mov.b64 %0, {%1, %2};" : "=l"(d) : "r"(lo), "r"(hi))

#define UNPACK2(lo, hi, v) \
    asm("mov.b64 {%0, %1}, %2;" : "=r"(lo), "=r"(hi) : "l"(v))

// ---- layer 0: [N,21] @ [21,128], write raw linear output + BN partials ------
__global__ __launch_bounds__(128) void layer0_kernel(
    const float* __restrict__ x, const int* __restrict__ idx,
    const float* __restrict__ W0, const float* __restrict__ b0)
{
    __shared__ float sA[64 * 21];
    const int t  = threadIdx.x;
    const int m0 = blockIdx.x * 64;

    for (int e = t; e < 64 * 21; e += 128) {
        int r = e / 21, k = e - r * 21;
        int m = m0 + r;
        float v = 0.f;
        if (m < NN) {
            int j = k / 3, c = k - j * 3;
            int nb = idx[m * 7 + j];
            v = x[nb * 3 + c];
        }
        sA[e] = v;
    }
    __syncthreads();

    float w[21];
#pragma unroll
    for (int k = 0; k < 21; k++) w[k] = W0[k * C + t];
    const float bias = b0[t];

    float s = 0.f, sq = 0.f;
    int rows = NN - m0; if (rows > 64) rows = 64;
    for (int r = 0; r < rows; r++) {
        float acc = bias;
#pragma unroll
        for (int k = 0; k < 21; k++) acc = fmaf(sA[r * 21 + k], w[k], acc);
        g_Y[(size_t)(m0 + r) * C + t] = acc;
        s += acc; sq += acc * acc;
    }
    g_psum[blockIdx.x * C + t] = s;
    g_psq [blockIdx.x * C + t] = sq;
}

// ---- BN stats finalize: mu/var over N, produce affine scale/shift -----------
__global__ void stats_kernel(int nblk, const float* __restrict__ g,
                             const float* __restrict__ be)
{
    const int n = threadIdx.x;
    float s = 0.f, q = 0.f;
    for (int b = 0; b < nblk; b++) {
        s += g_psum[b * C + n];
        q += g_psq [b * C + n];
    }
    const float inv_n = 1.f / (float)NN;
    float mu  = s * inv_n;
    float var = q * inv_n - mu * mu;        // biased variance (matches jnp.var)
    float sc  = g[n] * rsqrtf(var + EPSBN);
    g_scale[n] = sc;
    g_shift[n] = be[n] - mu * sc;
}

// ---- middle layer GEMM: [N,896] @ [896,128] ---------------------------------
// BM=128, BN=128, BK=32, 256 threads, per-thread 8x8 micro-tile in f32x2 pairs.
// Gather applies previous layer's BN affine + ReLU on the fly.
__global__ __launch_bounds__(256, 2) void gemm_mid_kernel(
    int cur, const int* __restrict__ idx,
    const float* __restrict__ W, const float* __restrict__ bias)
{
    const float* __restrict__ Hin  = g_Y + (size_t)cur * NN * C;
    float*       __restrict__ Yout = g_Y + (size_t)(cur ^ 1) * NN * C;

    __shared__ float sA[32 * 132];   // A tile transposed [k][m], pad 132 (16B-aligned rows)
    __shared__ float sB[32 * 128];   // B tile [k][n]
    __shared__ int   sIdx[128 * 7];
    __shared__ float sSc[128];
    __shared__ float sSh[128];

    const int t  = threadIdx.x;
    const int m0 = blockIdx.x * 128;

    for (int e = t; e < 128 * 7; e += 256) {
        int m = m0 + e / 7;
        sIdx[e] = (m < NN) ? idx[m * 7 + (e - (e / 7) * 7)] : 0;
    }
    if (t < 128) { sSc[t] = g_scale[t]; sSh[t] = g_shift[t]; }
    __syncthreads();

    unsigned long long acc[4][8];    // [row-pair][col] packed fp32x2 accumulators
#pragma unroll
    for (int i = 0; i < 4; i++)
#pragma unroll
        for (int jj = 0; jj < 8; jj++) acc[i][jj] = 0ull;

    const int ty = t >> 4;           // 0..15 : rows ty*8 .. ty*8+7
    const int tx = t & 15;           // 0..15 : cols tx*8 .. tx*8+7
    const int lrow = t >> 3;         // 0..31 : A-load row per pass
    const int lk   = (t & 7) << 2;   // 0,4,...,28 : A-load k offset (float4)

#pragma unroll 1
    for (int kt = 0; kt < 28; kt++) {
        const int j  = kt >> 2;            // neighbor slot (32*4 = 128 channels)
        const int cc = ((kt & 3) << 5) + lk;
        const float sc0 = sSc[cc], sc1 = sSc[cc + 1], sc2 = sSc[cc + 2], sc3 = sSc[cc + 3];
        const float sh0 = sSh[cc], sh1 = sSh[cc + 1], sh2 = sSh[cc + 2], sh3 = sSh[cc + 3];
        // gather A tile (apply prev-layer BN affine + ReLU)
#pragma unroll
        for (int p = 0; p < 4; p++) {
            int row = lrow + (p << 5);
            int nb  = sIdx[row * 7 + j];
            float4 v = *reinterpret_cast<const float4*>(&Hin[(size_t)nb * C + cc]);
            sA[(lk + 0) * 132 + row] = fmaxf(fmaf(v.x, sc0, sh0), 0.f);
            sA[(lk + 1) * 132 + row] = fmaxf(fmaf(v.y, sc1, sh1), 0.f);
            sA[(lk + 2) * 132 + row] = fmaxf(fmaf(v.z, sc2, sh2), 0.f);
            sA[(lk + 3) * 132 + row] = fmaxf(fmaf(v.w, sc3, sh3), 0.f);
        }
        // load B tile
#pragma unroll
        for (int p = 0; p < 4; p++) {
            int e  = (t + (p << 8)) << 2;
            int kr = e >> 7, nc = e & 127;
            *reinterpret_cast<float4*>(&sB[kr * 128 + nc]) =
                *reinterpret_cast<const float4*>(&W[(size_t)(kt * 32 + kr) * 128 + nc]);
        }
        __syncthreads();

#pragma unroll 8
        for (int k = 0; k < 32; k++) {
            const unsigned long long* ap =
                reinterpret_cast<const unsigned long long*>(&sA[k * 132 + (ty << 3)]);
            unsigned long long a0 = ap[0], a1 = ap[1], a2 = ap[2], a3 = ap[3];
            float4 bA = *reinterpret_cast<const float4*>(&sB[k * 128 + (tx << 3)]);
            float4 bB = *reinterpret_cast<const float4*>(&sB[k * 128 + (tx << 3) + 4]);
            unsigned long long b2[8];
            { unsigned u = __float_as_uint(bA.x); PACK2(b2[0], u, u); }
            { unsigned u = __float_as_uint(bA.y); PACK2(b2[1], u, u); }
            { unsigned u = __float_as_uint(bA.z); PACK2(b2[2], u, u); }
            { unsigned u = __float_as_uint(bA.w); PACK2(b2[3], u, u); }
            { unsigned u = __float_as_uint(bB.x); PACK2(b2[4], u, u); }
            { unsigned u = __float_as_uint(bB.y); PACK2(b2[5], u, u); }
            { unsigned u = __float_as_uint(bB.z); PACK2(b2[6], u, u); }
            { unsigned u = __float_as_uint(bB.w); PACK2(b2[7], u, u); }
#pragma unroll
            for (int jj = 0; jj < 8; jj++) {
                FMA2(acc[0][jj], a0, b2[jj]);
                FMA2(acc[1][jj], a1, b2[jj]);
                FMA2(acc[2][jj], a2, b2[jj]);
                FMA2(acc[3][jj], a3, b2[jj]);
            }
        }
        __syncthreads();
    }

    // epilogue: add bias, store raw pre-BN output, accumulate channel partials
    float bcol[8];
#pragma unroll
    for (int jj = 0; jj < 8; jj++) bcol[jj] = bias[(tx << 3) + jj];
    float colsum[8], colsq[8];
#pragma unroll
    for (int jj = 0; jj < 8; jj++) { colsum[jj] = 0.f; colsq[jj] = 0.f; }

#pragma unroll
    for (int ip = 0; ip < 4; ip++) {
        float ylo[8], yhi[8];
#pragma unroll
        for (int jj = 0; jj < 8; jj++) {
            unsigned lo, hi;
            UNPACK2(lo, hi, acc[ip][jj]);
            ylo[jj] = __uint_as_float(lo) + bcol[jj];
            yhi[jj] = __uint_as_float(hi) + bcol[jj];
        }
        int r0 = m0 + (ty << 3) + (ip << 1);
        if (r0 < NN) {
            float4* dst = reinterpret_cast<float4*>(&Yout[(size_t)r0 * C + (tx << 3)]);
            dst[0] = make_float4(ylo[0], ylo[1], ylo[2], ylo[3]);
            dst[1] = make_float4(ylo[4], ylo[5], ylo[6], ylo[7]);
#pragma unroll
            for (int jj = 0; jj < 8; jj++) { colsum[jj] += ylo[jj]; colsq[jj] += ylo[jj] * ylo[jj]; }
        }
        if (r0 + 1 < NN) {
            float4* dst = reinterpret_cast<float4*>(&Yout[(size_t)(r0 + 1) * C + (tx << 3)]);
            dst[0] = make_float4(yhi[0], yhi[1], yhi[2], yhi[3]);
            dst[1] = make_float4(yhi[4], yhi[5], yhi[6], yhi[7]);
#pragma unroll
            for (int jj = 0; jj < 8; jj++) { colsum[jj] += yhi[jj]; colsq[jj] += yhi[jj] * yhi[jj]; }
        }
    }

    // deterministic per-block channel reduction (reuse smem)
    float* redS = sA;        // 16*128 = 2048 floats (sA has 4224)
    float* redQ = sB;        // 16*128 = 2048 floats (sB has 4096)
#pragma unroll
    for (int jj = 0; jj < 8; jj++) {
        redS[ty * 128 + (tx << 3) + jj] = colsum[jj];
        redQ[ty * 128 + (tx << 3) + jj] = colsq[jj];
    }
    __syncthreads();
    if (t < 128) {
        float s = 0.f, q = 0.f;
#pragma unroll
        for (int u = 0; u < 16; u++) { s += redS[u * 128 + t]; q += redQ[u * 128 + t]; }
        g_psum[blockIdx.x * C + t] = s;
        g_psq [blockIdx.x * C + t] = q;
    }
}

// ---- final layer: [N,896] @ [896,36] + bias, no BN, write d_out -------------
__global__ __launch_bounds__(256, 2) void final_kernel(
    int cur, const int* __restrict__ idx,
    const float* __restrict__ Wl, const float* __restrict__ bl,
    float* __restrict__ out)
{
    const float* __restrict__ Hin = g_Y + (size_t)cur * NN * C;

    __shared__ float sA[32 * 132];
    __shared__ float sB[32 * 40];
    __shared__ int   sIdx[128 * 7];
    __shared__ float sSc[128];
    __shared__ float sSh[128];

    const int t  = threadIdx.x;
    const int m0 = blockIdx.x * 128;

    for (int e = t; e < 128 * 7; e += 256) {
        int m = m0 + e / 7;
        sIdx[e] = (m < NN) ? idx[m * 7 + (e - (e / 7) * 7)] : 0;
    }
    if (t < 128) { sSc[t] = g_scale[t]; sSh[t] = g_shift[t]; }
    __syncthreads();

    const int ty = t >> 4, tx = t & 15;
    const int lrow = t >> 3, lk = (t & 7) << 2;
    const bool active = (tx < 12);
    const int cbase = active ? tx * 3 : 0;

    float acc[8][3];
#pragma unroll
    for (int i = 0; i < 8; i++)
#pragma unroll
        for (int jj = 0; jj < 3; jj++) acc[i][jj] = 0.f;

#pragma unroll 1
    for (int kt = 0; kt < 28; kt++) {
        const int j  = kt >> 2;
        const int cc = ((kt & 3) << 5) + lk;
        const float sc0 = sSc[cc], sc1 = sSc[cc + 1], sc2 = sSc[cc + 2], sc3 = sSc[cc + 3];
        const float sh0 = sSh[cc], sh1 = sSh[cc + 1], sh2 = sSh[cc + 2], sh3 = sSh[cc + 3];
#pragma unroll
        for (int p = 0; p < 4; p++) {
            int row = lrow + (p << 5);
            int nb  = sIdx[row * 7 + j];
            float4 v = *reinterpret_cast<const float4*>(&Hin[(size_t)nb * C + cc]);
            sA[(lk + 0) * 132 + row] = fmaxf(fmaf(v.x, sc0, sh0), 0.f);
            sA[(lk + 1) * 132 + row] = fmaxf(fmaf(v.y, sc1, sh1), 0.f);
            sA[(lk + 2) * 132 + row] = fmaxf(fmaf(v.z, sc2, sh2), 0.f);
            sA[(lk + 3) * 132 + row] = fmaxf(fmaf(v.w, sc3, sh3), 0.f);
        }
        for (int e = t; e < 32 * 36; e += 256) {
            int kr = e / 36, nc = e - kr * 36;
            sB[kr * 40 + nc] = Wl[(size_t)(kt * 32 + kr) * 36 + nc];
        }
        __syncthreads();

#pragma unroll 8
        for (int k = 0; k < 32; k++) {
            float4 aA = *reinterpret_cast<const float4*>(&sA[k * 132 + (ty << 3)]);
            float4 aB = *reinterpret_cast<const float4*>(&sA[k * 132 + (ty << 3) + 4]);
            float af[8] = { aA.x, aA.y, aA.z, aA.w, aB.x, aB.y, aB.z, aB.w };
            float b0v = sB[k * 40 + cbase];
            float b1v = sB[k * 40 + cbase + 1];
            float b2v = sB[k * 40 + cbase + 2];
#pragma unroll
            for (int i = 0; i < 8; i++) {
                acc[i][0] = fmaf(af[i], b0v, acc[i][0]);
                acc[i][1] = fmaf(af[i], b1v, acc[i][1]);
                acc[i][2] = fmaf(af[i], b2v, acc[i][2]);
            }
        }
        __syncthreads();
    }

    if (active) {
        float bb0 = bl[cbase], bb1 = bl[cbase + 1], bb2 = bl[cbase + 2];
#pragma unroll
        for (int i = 0; i < 8; i++) {
            int m = m0 + (ty << 3) + i;
            if (m < NN) {
                out[(size_t)m * NCLS + cbase + 0] = acc[i][0] + bb0;
                out[(size_t)m * NCLS + cbase + 1] = acc[i][1] + bb1;
                out[(size_t)m * NCLS + cbase + 2] = acc[i][2] + bb2;
            }
        }
    }
}

// ---- launch ------------------------------------------------------------------
extern "C" void kernel_launch(void* const* d_in, const int* in_sizes, int n_in,
                              void* d_out, int out_size)
{
    const float* x   = (const float*)d_in[0];
    const int*   idx = (const int*)  d_in[1];
    const float* W0  = (const float*)d_in[2];
    const float* b0  = (const float*)d_in[3];
    const float* g0  = (const float*)d_in[4];
    const float* be0 = (const float*)d_in[5];
    const float* Wm  = (const float*)d_in[6];
    const float* bm  = (const float*)d_in[7];
    const float* gm  = (const float*)d_in[8];
    const float* bem = (const float*)d_in[9];
    const float* Wl  = (const float*)d_in[10];
    const float* bl  = (const float*)d_in[11];
    float* out = (float*)d_out;

    layer0_kernel<<<NB0, 128>>>(x, idx, W0, b0);
    stats_kernel<<<1, 128>>>(NB0, g0, be0);

    int cur = 0;
    for (int l = 0; l < 14; l++) {
        gemm_mid_kernel<<<NBM, 256>>>(cur, idx, Wm + (size_t)l * 896 * C, bm + (size_t)l * C);
        stats_kernel<<<1, 128>>>(NBM, gm + (size_t)l * C, bem + (size_t)l * C);
        cur ^= 1;
    }

    final_kernel<<<NBM, 256>>>(cur, idx, Wl, bl, out);
}

// round 3
// speedup vs baseline: 2.0329x; 2.0329x over previous
#include <cuda_runtime.h>
#include <cuda_bf16.h>
#include <cstdint>

// BrainSphereCNN on GB300 (compute_103 virtual target -> no tcgen05).
// Middle 14 layers [N,896]@[896,128] on warp-level mma.sync bf16 tensor ops
// with hi/lo split precision (Ahi*Bhi + Ahi*Blo + Alo*Bhi) for ~fp32 accuracy.
// Activations converted once per layer (BN affine + ReLU) to bf16 hi/lo; the
// GEMM gather is a pure bf16 copy. Deterministic BN reductions throughout.

#define NN    40962
#define C     128
#define NB0   641
#define NBM   321
#define NCLS  36
#define EPSBN 1e-5f
#define NLAY  14

// ---------------- device scratch ----------------
__device__ float          g_Y[(size_t)NN * C];            // pre-BN linear outputs
__device__ __nv_bfloat16  g_Xhi[(size_t)NN * C];          // post-BN/ReLU bf16 hi
__device__ __nv_bfloat16  g_Xlo[(size_t)NN * C];          // bf16 lo residual
__device__ __nv_bfloat16  g_Whi[(size_t)NLAY * C * 896];  // W^T hi  [l][n][k]
__device__ __nv_bfloat16  g_Wlo[(size_t)NLAY * C * 896];  // W^T lo
__device__ float          g_psum[NB0 * C];
__device__ float          g_psq [NB0 * C];
__device__ float          g_scale[C];
__device__ float          g_shift[C];

// ---------------- PTX helpers ----------------
__device__ __forceinline__ uint32_t smem_u32(const void* p) {
    uint32_t a;
    asm("{ .reg .u64 t; cvta.to.shared.u64 t, %1; cvt.u32.u64 %0, t; }" : "=r"(a) : "l"(p));
    return a;
}

#define LDSM_X4(r0, r1, r2, r3, addr) \
    asm volatile("ldmatrix.sync.aligned.m8n8.x4.shared.b16 {%0,%1,%2,%3}, [%4];" \
                 : "=r"(r0), "=r"(r1), "=r"(r2), "=r"(r3) : "r"(addr))

#define MMA16816(d0, d1, d2, d3, a0, a1, a2, a3, b0, b1) \
    asm volatile("mma.sync.aligned.m16n8k16.row.col.f32.bf16.bf16.f32 " \
                 "{%0,%1,%2,%3}, {%4,%5,%6,%7}, {%8,%9}, {%0,%1,%2,%3};" \
                 : "+f"(d0), "+f"(d1), "+f"(d2), "+f"(d3) \
                 : "r"(a0), "r"(a1), "r"(a2), "r"(a3), "r"(b0), "r"(b1))

// ---------------- weight prep: W[l][k][n] -> W^T hi/lo [l][n][k] bf16 ----------------
__global__ void prep_w(const float* __restrict__ Wm) {
    __shared__ float tile[32][33];
    const int l = blockIdx.z, k0 = blockIdx.x * 32, n0 = blockIdx.y * 32;
    const int tx = threadIdx.x, ty = threadIdx.y;
    tile[ty][tx] = Wm[((size_t)l * 896 + k0 + ty) * 128 + n0 + tx];
    __syncthreads();
    float w = tile[tx][ty];   // element (k0+tx, n0+ty)
    __nv_bfloat16 hi = __float2bfloat16_rn(w);
    __nv_bfloat16 lo = __float2bfloat16_rn(w - __bfloat162float(hi));
    size_t o = ((size_t)l * 128 + n0 + ty) * 896 + (k0 + tx);
    g_Whi[o] = hi;
    g_Wlo[o] = lo;
}

// ---------------- layer 0: [N,21]@[21,128] fp32 ----------------
__global__ __launch_bounds__(128) void layer0_kernel(
    const float* __restrict__ x, const int* __restrict__ idx,
    const float* __restrict__ W0, const float* __restrict__ b0)
{
    __shared__ float sA[64 * 21];
    const int t = threadIdx.x;
    const int m0 = blockIdx.x * 64;
    for (int e = t; e < 64 * 21; e += 128) {
        int r = e / 21, k = e - r * 21;
        int m = m0 + r;
        float v = 0.f;
        if (m < NN) {
            int j = k / 3, c = k - j * 3;
            v = x[idx[m * 7 + j] * 3 + c];
        }
        sA[e] = v;
    }
    __syncthreads();
    float w[21];
#pragma unroll
    for (int k = 0; k < 21; k++) w[k] = W0[k * C + t];
    const float bias = b0[t];
    float s = 0.f, sq = 0.f;
    int rows = NN - m0; if (rows > 64) rows = 64;
    for (int r = 0; r < rows; r++) {
        float acc = bias;
#pragma unroll
        for (int k = 0; k < 21; k++) acc = fmaf(sA[r * 21 + k], w[k], acc);
        g_Y[(size_t)(m0 + r) * C + t] = acc;
        s += acc; sq += acc * acc;
    }
    g_psum[blockIdx.x * C + t] = s;
    g_psq [blockIdx.x * C + t] = sq;
}

// ---------------- BN stats finalize (parallel) ----------------
__global__ __launch_bounds__(1024) void stats_final(int nblk, const float* __restrict__ g,
                                                    const float* __restrict__ be)
{
    __shared__ float sS[8][128], sQ[8][128];
    const int t = threadIdx.x;
    const int ch = t & 127, sl = t >> 7;
    float s = 0.f, q = 0.f;
    for (int b = sl; b < nblk; b += 8) {
        s += g_psum[b * C + ch];
        q += g_psq [b * C + ch];
    }
    sS[sl][ch] = s; sQ[sl][ch] = q;
    __syncthreads();
    if (t < 128) {
        float S = 0.f, Q = 0.f;
#pragma unroll
        for (int u = 0; u < 8; u++) { S += sS[u][t]; Q += sQ[u][t]; }
        const float inv_n = 1.f / (float)NN;
        float mu  = S * inv_n;
        float var = Q * inv_n - mu * mu;
        float sc  = g[t] * rsqrtf(var + EPSBN);
        g_scale[t] = sc;
        g_shift[t] = be[t] - mu * sc;
    }
}

// ---------------- convert: Y -> bf16 hi/lo activations (affine + ReLU) --------------
__global__ __launch_bounds__(256) void convert_kernel() {
    int e = blockIdx.x * 256 + threadIdx.x;      // one float4 (4 channels) per thread
    if (e >= NN * 32) return;
    const int c0 = (e & 31) * 4;
    float4 y = ((const float4*)g_Y)[e];
    float h0 = fmaxf(fmaf(y.x, g_scale[c0 + 0], g_shift[c0 + 0]), 0.f);
    float h1 = fmaxf(fmaf(y.y, g_scale[c0 + 1], g_shift[c0 + 1]), 0.f);
    float h2 = fmaxf(fmaf(y.z, g_scale[c0 + 2], g_shift[c0 + 2]), 0.f);
    float h3 = fmaxf(fmaf(y.w, g_scale[c0 + 3], g_shift[c0 + 3]), 0.f);
    __nv_bfloat16 a0 = __float2bfloat16_rn(h0), a1 = __float2bfloat16_rn(h1);
    __nv_bfloat16 a2 = __float2bfloat16_rn(h2), a3 = __float2bfloat16_rn(h3);
    __nv_bfloat16 l0 = __float2bfloat16_rn(h0 - __bfloat162float(a0));
    __nv_bfloat16 l1 = __float2bfloat16_rn(h1 - __bfloat162float(a1));
    __nv_bfloat16 l2 = __float2bfloat16_rn(h2 - __bfloat162float(a2));
    __nv_bfloat16 l3 = __float2bfloat16_rn(h3 - __bfloat162float(a3));
    uint2 ph, pl;
    ph.x = (uint32_t)__bfloat16_as_ushort(a0) | ((uint32_t)__bfloat16_as_ushort(a1) << 16);
    ph.y = (uint32_t)__bfloat16_as_ushort(a2) | ((uint32_t)__bfloat16_as_ushort(a3) << 16);
    pl.x = (uint32_t)__bfloat16_as_ushort(l0) | ((uint32_t)__bfloat16_as_ushort(l1) << 16);
    pl.y = (uint32_t)__bfloat16_as_ushort(l2) | ((uint32_t)__bfloat16_as_ushort(l3) << 16);
    ((uint2*)g_Xhi)[e] = ph;
    ((uint2*)g_Xlo)[e] = pl;
}

// ---------------- middle layer: mma.sync bf16 hi/lo GEMM [N,896]@[896,128] ----------
// 512 threads (16 warps, 4x4 grid of 32x32 warp tiles), K chunks of 64.
// smem pitch: 72 halves (144 B) per row -> conflict-free ldmatrix.
#define PITCH  72
#define SM_AHI 0                        // 128 x 72 halves = 18432 B
#define SM_ALO 18432
#define SM_BHI 36864
#define SM_BLO 55296
#define SM_IDX 73728                    // 896 ints = 3584 B
#define SM_BIAS 77312                   // 128 floats
#define SM_REDS 77824                   // 4*128 floats
#define SM_REDQ 79872                   // 4*128 floats
#define GEMM_SMEM 81920
// epilogue stage (reuses A/B region): 128 rows x 132 floats = 67584 B
#define STAGE_PITCH 132

__global__ void __launch_bounds__(512, 1)
gemm_mma(int layer, const int* __restrict__ idx, const float* __restrict__ bias)
{
    extern __shared__ char smp[];
    const uint32_t sb = smem_u32(smp);
    const int t    = threadIdx.x;
    const int lane = t & 31;
    const int wid  = t >> 5;
    const int wm   = wid >> 2;           // 0..3 : rows wm*32..+31
    const int wn   = wid & 3;            // 0..3 : cols wn*32..+31
    const int m0   = blockIdx.x * 128;

    const __nv_bfloat16* __restrict__ Whi = g_Whi + (size_t)layer * C * 896;
    const __nv_bfloat16* __restrict__ Wlo = g_Wlo + (size_t)layer * C * 896;

    int* sIdx = (int*)(smp + SM_IDX);
    float* sBias = (float*)(smp + SM_BIAS);
    for (int e = t; e < 896; e += 512) {
        int row = e / 7, j = e - row * 7;
        int m = m0 + row;
        sIdx[e] = (m < NN) ? idx[m * 7 + j] : 0;
    }
    if (t < 128) sBias[t] = bias[t];
    __syncthreads();

    // gather thread mapping: row = t>>2 (0..127), q = t&3 (16-half segment)
    const int grow = t >> 2;
    const int gq   = t & 3;

    float d[2][4][4];
#pragma unroll
    for (int mt = 0; mt < 2; mt++)
#pragma unroll
        for (int nt = 0; nt < 4; nt++)
#pragma unroll
            for (int i = 0; i < 4; i++) d[mt][nt][i] = 0.f;

    // precomputed ldmatrix lane addressing
    const int a_row  = wm * 32 + (lane & 15);
    const int a_koff = (lane >> 4) * 8;
    const int b_n    = wn * 32 + (lane & 7) + ((lane >> 4) & 1) * 8;
    const int b_koff = ((lane >> 3) & 1) * 8;

    for (int c = 0; c < 14; c++) {
        const int j = c >> 1, h = c & 1;
        // ---- gather A (bf16 copy) + load B ----
        {
            const int nb = sIdx[grow * 7 + j];
            const uint4* aH = (const uint4*)(g_Xhi + (size_t)nb * C + h * 64);
            const uint4* aL = (const uint4*)(g_Xlo + (size_t)nb * C + h * 64);
            const uint4* bH = (const uint4*)(Whi + (size_t)grow * 896 + c * 64);
            const uint4* bL = (const uint4*)(Wlo + (size_t)grow * 896 + c * 64);
            uint4 va0 = aH[gq * 2], va1 = aH[gq * 2 + 1];
            uint4 vl0 = aL[gq * 2], vl1 = aL[gq * 2 + 1];
            uint4 wb0 = bH[gq * 2], wb1 = bH[gq * 2 + 1];
            uint4 wl0 = bL[gq * 2], wl1 = bL[gq * 2 + 1];
            char* pA = smp + SM_AHI + grow * (PITCH * 2) + gq * 32;
            char* pAl = smp + SM_ALO + grow * (PITCH * 2) + gq * 32;
            char* pB = smp + SM_BHI + grow * (PITCH * 2) + gq * 32;
            char* pBl = smp + SM_BLO + grow * (PITCH * 2) + gq * 32;
            *(uint4*)(pA) = va0;       *(uint4*)(pA + 16) = va1;
            *(uint4*)(pAl) = vl0;      *(uint4*)(pAl + 16) = vl1;
            *(uint4*)(pB) = wb0;       *(uint4*)(pB + 16) = wb1;
            *(uint4*)(pBl) = wl0;      *(uint4*)(pBl + 16) = wl1;
        }
        __syncthreads();

        // ---- MMA over 4 k-steps of 16 ----
#pragma unroll
        for (int ks = 0; ks < 4; ks++) {
            uint32_t ahi[2][4], alo[2][4];
#pragma unroll
            for (int mt = 0; mt < 2; mt++) {
                uint32_t ra = sb + SM_AHI + ((a_row + mt * 16) * PITCH + ks * 16 + a_koff) * 2;
                LDSM_X4(ahi[mt][0], ahi[mt][1], ahi[mt][2], ahi[mt][3], ra);
                uint32_t rl = sb + SM_ALO + ((a_row + mt * 16) * PITCH + ks * 16 + a_koff) * 2;
                LDSM_X4(alo[mt][0], alo[mt][1], alo[mt][2], alo[mt][3], rl);
            }
            uint32_t bhi[4][2], blo[4][2];
#pragma unroll
            for (int p = 0; p < 2; p++) {
                uint32_t rb = sb + SM_BHI + ((b_n + p * 16) * PITCH + ks * 16 + b_koff) * 2;
                uint32_t r0, r1, r2, r3;
                LDSM_X4(r0, r1, r2, r3, rb);
                bhi[2 * p][0] = r0; bhi[2 * p][1] = r1;
                bhi[2 * p + 1][0] = r2; bhi[2 * p + 1][1] = r3;
                uint32_t rbl = sb + SM_BLO + ((b_n + p * 16) * PITCH + ks * 16 + b_koff) * 2;
                LDSM_X4(r0, r1, r2, r3, rbl);
                blo[2 * p][0] = r0; blo[2 * p][1] = r1;
                blo[2 * p + 1][0] = r2; blo[2 * p + 1][1] = r3;
            }
#pragma unroll
            for (int mt = 0; mt < 2; mt++)
#pragma unroll
                for (int nt = 0; nt < 4; nt++) {
                    MMA16816(d[mt][nt][0], d[mt][nt][1], d[mt][nt][2], d[mt][nt][3],
                             ahi[mt][0], ahi[mt][1], ahi[mt][2], ahi[mt][3],
                             bhi[nt][0], bhi[nt][1]);
                    MMA16816(d[mt][nt][0], d[mt][nt][1], d[mt][nt][2], d[mt][nt][3],
                             ahi[mt][0], ahi[mt][1], ahi[mt][2], ahi[mt][3],
                             blo[nt][0], blo[nt][1]);
                    MMA16816(d[mt][nt][0], d[mt][nt][1], d[mt][nt][2], d[mt][nt][3],
                             alo[mt][0], alo[mt][1], alo[mt][2], alo[mt][3],
                             bhi[nt][0], bhi[nt][1]);
                }
        }
        __syncthreads();
    }

    // ---- epilogue: stage to smem, add bias, store Y, deterministic BN partials ----
    float* stage = (float*)smp;           // reuse A/B region (67.6 KB)
    // warp tile rows: wm*32 + mt*16 + (lane>>2) + (i>=2)*8 ; cols: wn*32 + nt*8 + (lane&3)*2 + (i&1)
#pragma unroll
    for (int mt = 0; mt < 2; mt++)
#pragma unroll
        for (int nt = 0; nt < 4; nt++)
#pragma unroll
            for (int i = 0; i < 4; i++) {
                int row = wm * 32 + mt * 16 + (lane >> 2) + ((i >> 1) << 3);
                int col = wn * 32 + nt * 8 + ((lane & 3) << 1) + (i & 1);
                stage[row * STAGE_PITCH + col] = d[mt][nt][i] + sBias[col];
            }
    __syncthreads();

    {
        const int col = t & 127, part = t >> 7;   // 4 parts x 32 rows
        float s = 0.f, q = 0.f;
        for (int r = 0; r < 32; r++) {
            int row = part * 32 + r;
            int m = m0 + row;
            float v = stage[row * STAGE_PITCH + col];
            if (m < NN) {
                g_Y[(size_t)m * C + col] = v;
                s += v; q += v * v;
            }
        }
        ((float*)(smp + SM_REDS))[part * 128 + col] = s;
        ((float*)(smp + SM_REDQ))[part * 128 + col] = q;
    }
    __syncthreads();
    if (t < 128) {
        float s = 0.f, q = 0.f;
#pragma unroll
        for (int u = 0; u < 4; u++) {
            s += ((float*)(smp + SM_REDS))[u * 128 + t];
            q += ((float*)(smp + SM_REDQ))[u * 128 + t];
        }
        g_psum[blockIdx.x * C + t] = s;
        g_psq [blockIdx.x * C + t] = q;
    }
}

// ---------------- final layer: [N,896]@[896,36] fp32, affine+ReLU in gather ---------
__global__ __launch_bounds__(256, 2) void final_kernel(
    const int* __restrict__ idx,
    const float* __restrict__ Wl, const float* __restrict__ bl,
    float* __restrict__ out)
{
    const float* __restrict__ Hin = g_Y;
    __shared__ float sA[32 * 132];
    __shared__ float sB[32 * 40];
    __shared__ int   sIdx[128 * 7];
    __shared__ float sSc[128];
    __shared__ float sSh[128];

    const int t  = threadIdx.x;
    const int m0 = blockIdx.x * 128;
    for (int e = t; e < 128 * 7; e += 256) {
        int m = m0 + e / 7;
        sIdx[e] = (m < NN) ? idx[m * 7 + (e - (e / 7) * 7)] : 0;
    }
    if (t < 128) { sSc[t] = g_scale[t]; sSh[t] = g_shift[t]; }
    __syncthreads();

    const int ty = t >> 4, tx = t & 15;
    const int lrow = t >> 3, lk = (t & 7) << 2;
    const bool active = (tx < 12);
    const int cbase = active ? tx * 3 : 0;

    float acc[8][3];
#pragma unroll
    for (int i = 0; i < 8; i++)
#pragma unroll
        for (int jj = 0; jj < 3; jj++) acc[i][jj] = 0.f;

#pragma unroll 1
    for (int kt = 0; kt < 28; kt++) {
        const int j  = kt >> 2;
        const int cc = ((kt & 3) << 5) + lk;
        const float sc0 = sSc[cc], sc1 = sSc[cc + 1], sc2 = sSc[cc + 2], sc3 = sSc[cc + 3];
        const float sh0 = sSh[cc], sh1 = sSh[cc + 1], sh2 = sSh[cc + 2], sh3 = sSh[cc + 3];
#pragma unroll
        for (int p = 0; p < 4; p++) {
            int row = lrow + (p << 5);
            int nb  = sIdx[row * 7 + j];
            float4 v = *reinterpret_cast<const float4*>(&Hin[(size_t)nb * C + cc]);
            sA[(lk + 0) * 132 + row] = fmaxf(fmaf(v.x, sc0, sh0), 0.f);
            sA[(lk + 1) * 132 + row] = fmaxf(fmaf(v.y, sc1, sh1), 0.f);
            sA[(lk + 2) * 132 + row] = fmaxf(fmaf(v.z, sc2, sh2), 0.f);
            sA[(lk + 3) * 132 + row] = fmaxf(fmaf(v.w, sc3, sh3), 0.f);
        }
        for (int e = t; e < 32 * 36; e += 256) {
            int kr = e / 36, nc = e - kr * 36;
            sB[kr * 40 + nc] = Wl[(size_t)(kt * 32 + kr) * 36 + nc];
        }
        __syncthreads();
#pragma unroll 8
        for (int k = 0; k < 32; k++) {
            float4 aA = *reinterpret_cast<const float4*>(&sA[k * 132 + (ty << 3)]);
            float4 aB = *reinterpret_cast<const float4*>(&sA[k * 132 + (ty << 3) + 4]);
            float af[8] = { aA.x, aA.y, aA.z, aA.w, aB.x, aB.y, aB.z, aB.w };
            float b0v = sB[k * 40 + cbase];
            float b1v = sB[k * 40 + cbase + 1];
            float b2v = sB[k * 40 + cbase + 2];
#pragma unroll
            for (int i = 0; i < 8; i++) {
                acc[i][0] = fmaf(af[i], b0v, acc[i][0]);
                acc[i][1] = fmaf(af[i], b1v, acc[i][1]);
                acc[i][2] = fmaf(af[i], b2v, acc[i][2]);
            }
        }
        __syncthreads();
    }

    if (active) {
        float bb0 = bl[cbase], bb1 = bl[cbase + 1], bb2 = bl[cbase + 2];
#pragma unroll
        for (int i = 0; i < 8; i++) {
            int m = m0 + (ty << 3) + i;
            if (m < NN) {
                out[(size_t)m * NCLS + cbase + 0] = acc[i][0] + bb0;
                out[(size_t)m * NCLS + cbase + 1] = acc[i][1] + bb1;
                out[(size_t)m * NCLS + cbase + 2] = acc[i][2] + bb2;
            }
        }
    }
}

// ---------------- launch ----------------
extern "C" void kernel_launch(void* const* d_in, const int* in_sizes, int n_in,
                              void* d_out, int out_size)
{
    const float* x   = (const float*)d_in[0];
    const int*   idx = (const int*)  d_in[1];
    const float* W0  = (const float*)d_in[2];
    const float* b0  = (const float*)d_in[3];
    const float* g0  = (const float*)d_in[4];
    const float* be0 = (const float*)d_in[5];
    const float* Wm  = (const float*)d_in[6];
    const float* bm  = (const float*)d_in[7];
    const float* gm  = (const float*)d_in[8];
    const float* bem = (const float*)d_in[9];
    const float* Wl  = (const float*)d_in[10];
    const float* bl  = (const float*)d_in[11];
    float* out = (float*)d_out;

    static int smem_set = 0;
    if (!smem_set) {
        cudaFuncSetAttribute(gemm_mma, cudaFuncAttributeMaxDynamicSharedMemorySize, GEMM_SMEM);
        smem_set = 1;
    }

    prep_w<<<dim3(28, 4, NLAY), dim3(32, 32)>>>(Wm);
    layer0_kernel<<<NB0, 128>>>(x, idx, W0, b0);
    stats_final<<<1, 1024>>>(NB0, g0, be0);
    convert_kernel<<<(NN * 32 + 255) / 256, 256>>>();

    for (int l = 0; l < NLAY; l++) {
        gemm_mma<<<NBM, 512, GEMM_SMEM>>>(l, idx, bm + (size_t)l * C);
        stats_final<<<1, 1024>>>(NBM, gm + (size_t)l * C, bem + (size_t)l * C);
        if (l < NLAY - 1)
            convert_kernel<<<(NN * 32 + 255) / 256, 256>>>();
    }

    final_kernel<<<NBM, 256>>>(idx, Wl, bl, out);
}

// round 5
// speedup vs baseline: 2.1286x; 1.0471x over previous
#include <cuda_runtime.h>
#include <cuda_bf16.h>
#include <cstdint>

// BrainSphereCNN on GB300 (compute_103 virtual target -> warp mma.sync path).
// Middle 14 layers [N,896]@[896,128] on mma.sync bf16 with hi/lo split
// (Ahi*Bhi + Ahi*Blo + Alo*Bhi). Round 5: cp.async double-buffered pipeline,
// FIXED loader coverage (2x16B per thread per buffer = full 128B rows).

#define NN    40962
#define C     128
#define NB0   641
#define NBM   321
#define NCLS  36
#define EPSBN 1e-5f
#define NLAY  14

// ---------------- device scratch ----------------
__device__ float          g_Y[(size_t)NN * C];
__device__ __nv_bfloat16  g_Xhi[(size_t)NN * C];
__device__ __nv_bfloat16  g_Xlo[(size_t)NN * C];
__device__ __nv_bfloat16  g_Whi[(size_t)NLAY * C * 896];  // W^T hi [l][n][k]
__device__ __nv_bfloat16  g_Wlo[(size_t)NLAY * C * 896];
__device__ float          g_psum[NB0 * C];
__device__ float          g_psq [NB0 * C];
__device__ float          g_scale[C];
__device__ float          g_shift[C];

// ---------------- PTX helpers ----------------
__device__ __forceinline__ uint32_t smem_u32(const void* p) {
    uint32_t a;
    asm("{ .reg .u64 t; cvta.to.shared.u64 t, %1; cvt.u32.u64 %0, t; }" : "=r"(a) : "l"(p));
    return a;
}

#define LDSM_X4(r0, r1, r2, r3, addr) \
    asm volatile("ldmatrix.sync.aligned.m8n8.x4.shared.b16 {%0,%1,%2,%3}, [%4];" \
                 : "=r"(r0), "=r"(r1), "=r"(r2), "=r"(r3) : "r"(addr))

#define MMA16816(d0, d1, d2, d3, a0, a1, a2, a3, b0, b1) \
    asm volatile("mma.sync.aligned.m16n8k16.row.col.f32.bf16.bf16.f32 " \
                 "{%0,%1,%2,%3}, {%4,%5,%6,%7}, {%8,%9}, {%0,%1,%2,%3};" \
                 : "+f"(d0), "+f"(d1), "+f"(d2), "+f"(d3) \
                 : "r"(a0), "r"(a1), "r"(a2), "r"(a3), "r"(b0), "r"(b1))

#define CP16(dst, src) \
    asm volatile("cp.async.cg.shared.global [%0], [%1], 16;" :: "r"(dst), "l"(src) : "memory")
#define CP_COMMIT() asm volatile("cp.async.commit_group;" ::: "memory")
#define CP_WAIT(n)  asm volatile("cp.async.wait_group %0;" :: "n"(n) : "memory")

// ---------------- weight prep: W[l][k][n] -> W^T hi/lo [l][n][k] bf16 ----------------
__global__ void prep_w(const float* __restrict__ Wm) {
    __shared__ float tile[32][33];
    const int l = blockIdx.z, k0 = blockIdx.x * 32, n0 = blockIdx.y * 32;
    const int tx = threadIdx.x, ty = threadIdx.y;
    tile[ty][tx] = Wm[((size_t)l * 896 + k0 + ty) * 128 + n0 + tx];
    __syncthreads();
    float w = tile[tx][ty];
    __nv_bfloat16 hi = __float2bfloat16_rn(w);
    __nv_bfloat16 lo = __float2bfloat16_rn(w - __bfloat162float(hi));
    size_t o = ((size_t)l * 128 + n0 + ty) * 896 + (k0 + tx);
    g_Whi[o] = hi;
    g_Wlo[o] = lo;
}

// ---------------- layer 0: [N,21]@[21,128] fp32 ----------------
__global__ __launch_bounds__(128) void layer0_kernel(
    const float* __restrict__ x, const int* __restrict__ idx,
    const float* __restrict__ W0, const float* __restrict__ b0)
{
    __shared__ float sA[64 * 21];
    const int t = threadIdx.x;
    const int m0 = blockIdx.x * 64;
    for (int e = t; e < 64 * 21; e += 128) {
        int r = e / 21, k = e - r * 21;
        int m = m0 + r;
        float v = 0.f;
        if (m < NN) {
            int j = k / 3, c = k - j * 3;
            v = x[idx[m * 7 + j] * 3 + c];
        }
        sA[e] = v;
    }
    __syncthreads();
    float w[21];
#pragma unroll
    for (int k = 0; k < 21; k++) w[k] = W0[k * C + t];
    const float bias = b0[t];
    float s = 0.f, sq = 0.f;
    int rows = NN - m0; if (rows > 64) rows = 64;
    for (int r = 0; r < rows; r++) {
        float acc = bias;
#pragma unroll
        for (int k = 0; k < 21; k++) acc = fmaf(sA[r * 21 + k], w[k], acc);
        g_Y[(size_t)(m0 + r) * C + t] = acc;
        s += acc; sq += acc * acc;
    }
    g_psum[blockIdx.x * C + t] = s;
    g_psq [blockIdx.x * C + t] = sq;
}

// ---------------- BN stats finalize ----------------
__global__ __launch_bounds__(1024) void stats_final(int nblk, const float* __restrict__ g,
                                                    const float* __restrict__ be)
{
    __shared__ float sS[8][128], sQ[8][128];
    const int t = threadIdx.x;
    const int ch = t & 127, sl = t >> 7;
    float s = 0.f, q = 0.f;
    for (int b = sl; b < nblk; b += 8) {
        s += g_psum[b * C + ch];
        q += g_psq [b * C + ch];
    }
    sS[sl][ch] = s; sQ[sl][ch] = q;
    __syncthreads();
    if (t < 128) {
        float S = 0.f, Q = 0.f;
#pragma unroll
        for (int u = 0; u < 8; u++) { S += sS[u][t]; Q += sQ[u][t]; }
        const float inv_n = 1.f / (float)NN;
        float mu  = S * inv_n;
        float var = Q * inv_n - mu * mu;
        float sc  = g[t] * rsqrtf(var + EPSBN);
        g_scale[t] = sc;
        g_shift[t] = be[t] - mu * sc;
    }
}

// ---------------- convert: Y -> bf16 hi/lo (affine + ReLU) ----------------
__global__ __launch_bounds__(256) void convert_kernel() {
    int e = blockIdx.x * 256 + threadIdx.x;
    if (e >= NN * 32) return;
    const int c0 = (e & 31) * 4;
    float4 y = ((const float4*)g_Y)[e];
    float h0 = fmaxf(fmaf(y.x, g_scale[c0 + 0], g_shift[c0 + 0]), 0.f);
    float h1 = fmaxf(fmaf(y.y, g_scale[c0 + 1], g_shift[c0 + 1]), 0.f);
    float h2 = fmaxf(fmaf(y.z, g_scale[c0 + 2], g_shift[c0 + 2]), 0.f);
    float h3 = fmaxf(fmaf(y.w, g_scale[c0 + 3], g_shift[c0 + 3]), 0.f);
    __nv_bfloat16 a0 = __float2bfloat16_rn(h0), a1 = __float2bfloat16_rn(h1);
    __nv_bfloat16 a2 = __float2bfloat16_rn(h2), a3 = __float2bfloat16_rn(h3);
    __nv_bfloat16 l0 = __float2bfloat16_rn(h0 - __bfloat162float(a0));
    __nv_bfloat16 l1 = __float2bfloat16_rn(h1 - __bfloat162float(a1));
    __nv_bfloat16 l2 = __float2bfloat16_rn(h2 - __bfloat162float(a2));
    __nv_bfloat16 l3 = __float2bfloat16_rn(h3 - __bfloat162float(a3));
    uint2 ph, pl;
    ph.x = (uint32_t)__bfloat16_as_ushort(a0) | ((uint32_t)__bfloat16_as_ushort(a1) << 16);
    ph.y = (uint32_t)__bfloat16_as_ushort(a2) | ((uint32_t)__bfloat16_as_ushort(a3) << 16);
    pl.x = (uint32_t)__bfloat16_as_ushort(l0) | ((uint32_t)__bfloat16_as_ushort(l1) << 16);
    pl.y = (uint32_t)__bfloat16_as_ushort(l2) | ((uint32_t)__bfloat16_as_ushort(l3) << 16);
    ((uint2*)g_Xhi)[e] = ph;
    ((uint2*)g_Xlo)[e] = pl;
}

// ---------------- middle layer GEMM: cp.async double-buffered ----------------
// 512 threads, 16 warps (4x4 warp grid, 32x32 tiles), K chunks of 64 halves.
// Two smem stages, each: Ahi | Alo | Bhi | Blo at 128 rows x 72-half pitch.
#define PITCH   72
#define BUFB    18432                    // one buffer: 128 * 72 * 2 bytes
#define STAGEB  (4 * BUFB)               // 73728
#define SM_IDX  (2 * STAGEB)             // 147456, 896 ints
#define SM_BIAS (SM_IDX + 3584)
#define SM_REDS (SM_BIAS + 512)
#define SM_REDQ (SM_REDS + 2048)
#define GEMM_SMEM (SM_REDQ + 2048)       // 155648
#define STAGE_PITCH 132

__global__ void __launch_bounds__(512, 1)
gemm_mma(int layer, const int* __restrict__ idx, const float* __restrict__ bias)
{
    extern __shared__ char smp[];
    const uint32_t sb = smem_u32(smp);
    const int t    = threadIdx.x;
    const int lane = t & 31;
    const int wid  = t >> 5;
    const int wm   = wid >> 2;
    const int wn   = wid & 3;
    const int m0   = blockIdx.x * 128;

    const __nv_bfloat16* __restrict__ Whi = g_Whi + (size_t)layer * C * 896;
    const __nv_bfloat16* __restrict__ Wlo = g_Wlo + (size_t)layer * C * 896;

    int* sIdx = (int*)(smp + SM_IDX);
    float* sBias = (float*)(smp + SM_BIAS);
    for (int e = t; e < 896; e += 512) {
        int row = e / 7, j = e - row * 7;
        int m = m0 + row;
        sIdx[e] = (m < NN) ? idx[m * 7 + j] : 0;
    }
    if (t < 128) sBias[t] = bias[t];
    __syncthreads();

    // loader mapping: row = t>>2 (0..127), q = t&3; each thread copies 32B
    // per buffer (two 16B cp.async) -> 4 threads cover the full 128B row.
    const int grow = t >> 2;
    const int gq   = t & 3;
    const uint32_t dstOff = (uint32_t)grow * (PITCH * 2) + (uint32_t)gq * 32;
    const __nv_bfloat16* bHrow = Whi + (size_t)grow * 896;
    const __nv_bfloat16* bLrow = Wlo + (size_t)grow * 896;

    auto issue = [&](int c, int s) {
        const int j = c >> 1, h = c & 1;
        const int nb = sIdx[grow * 7 + j];
        const char* aH = (const char*)(g_Xhi + (size_t)nb * C + h * 64) + gq * 32;
        const char* aL = (const char*)(g_Xlo + (size_t)nb * C + h * 64) + gq * 32;
        const char* bH = (const char*)(bHrow + c * 64) + gq * 32;
        const char* bL = (const char*)(bLrow + c * 64) + gq * 32;
        uint32_t base = sb + s * STAGEB + dstOff;
        CP16(base,                aH);
        CP16(base + 16,           aH + 16);
        CP16(base + BUFB,         aL);
        CP16(base + BUFB + 16,    aL + 16);
        CP16(base + 2 * BUFB,     bH);
        CP16(base + 2 * BUFB + 16, bH + 16);
        CP16(base + 3 * BUFB,     bL);
        CP16(base + 3 * BUFB + 16, bL + 16);
        CP_COMMIT();
    };

    float d[2][4][4];
#pragma unroll
    for (int mt = 0; mt < 2; mt++)
#pragma unroll
        for (int nt = 0; nt < 4; nt++)
#pragma unroll
            for (int i = 0; i < 4; i++) d[mt][nt][i] = 0.f;

    const int a_row  = wm * 32 + (lane & 15);
    const int a_koff = (lane >> 4) * 8;
    const int b_n    = wn * 32 + (lane & 7) + ((lane >> 4) & 1) * 8;
    const int b_koff = ((lane >> 3) & 1) * 8;

    issue(0, 0);

    for (int c = 0; c < 14; c++) {
        const int s = c & 1;
        if (c + 1 < 14) {
            issue(c + 1, s ^ 1);
            CP_WAIT(1);
        } else {
            CP_WAIT(0);
        }
        __syncthreads();

        const uint32_t sA = sb + s * STAGEB;
        const uint32_t sAl = sA + BUFB;
        const uint32_t sB = sA + 2 * BUFB;
        const uint32_t sBl = sA + 3 * BUFB;

#pragma unroll
        for (int ks = 0; ks < 4; ks++) {
            uint32_t ahi[2][4], alo[2][4];
#pragma unroll
            for (int mt = 0; mt < 2; mt++) {
                uint32_t ra = sA + ((a_row + mt * 16) * PITCH + ks * 16 + a_koff) * 2;
                LDSM_X4(ahi[mt][0], ahi[mt][1], ahi[mt][2], ahi[mt][3], ra);
                uint32_t rl = sAl + ((a_row + mt * 16) * PITCH + ks * 16 + a_koff) * 2;
                LDSM_X4(alo[mt][0], alo[mt][1], alo[mt][2], alo[mt][3], rl);
            }
            uint32_t bhi[4][2], blo[4][2];
#pragma unroll
            for (int p = 0; p < 2; p++) {
                uint32_t rb = sB + ((b_n + p * 16) * PITCH + ks * 16 + b_koff) * 2;
                uint32_t r0, r1, r2, r3;
                LDSM_X4(r0, r1, r2, r3, rb);
                bhi[2 * p][0] = r0; bhi[2 * p][1] = r1;
                bhi[2 * p + 1][0] = r2; bhi[2 * p + 1][1] = r3;
                uint32_t rbl = sBl + ((b_n + p * 16) * PITCH + ks * 16 + b_koff) * 2;
                LDSM_X4(r0, r1, r2, r3, rbl);
                blo[2 * p][0] = r0; blo[2 * p][1] = r1;
                blo[2 * p + 1][0] = r2; blo[2 * p + 1][1] = r3;
            }
#pragma unroll
            for (int mt = 0; mt < 2; mt++)
#pragma unroll
                for (int nt = 0; nt < 4; nt++) {
                    MMA16816(d[mt][nt][0], d[mt][nt][1], d[mt][nt][2], d[mt][nt][3],
                             ahi[mt][0], ahi[mt][1], ahi[mt][2], ahi[mt][3],
                             bhi[nt][0], bhi[nt][1]);
                    MMA16816(d[mt][nt][0], d[mt][nt][1], d[mt][nt][2], d[mt][nt][3],
                             ahi[mt][0], ahi[mt][1], ahi[mt][2], ahi[mt][3],
                             blo[nt][0], blo[nt][1]);
                    MMA16816(d[mt][nt][0], d[mt][nt][1], d[mt][nt][2], d[mt][nt][3],
                             alo[mt][0], alo[mt][1], alo[mt][2], alo[mt][3],
                             bhi[nt][0], bhi[nt][1]);
                }
        }
        __syncthreads();   // all warps done with stage s before it is refilled
    }

    // ---- epilogue: stage, bias, store Y, deterministic BN partials ----
    float* stage = (float*)smp;
#pragma unroll
    for (int mt = 0; mt < 2; mt++)
#pragma unroll
        for (int nt = 0; nt < 4; nt++)
#pragma unroll
            for (int i = 0; i < 4; i++) {
                int row = wm * 32 + mt * 16 + (lane >> 2) + ((i >> 1) << 3);
                int col = wn * 32 + nt * 8 + ((lane & 3) << 1) + (i & 1);
                stage[row * STAGE_PITCH + col] = d[mt][nt][i] + sBias[col];
            }
    __syncthreads();

    {
        const int col = t & 127, part = t >> 7;
        float s = 0.f, q = 0.f;
        for (int r = 0; r < 32; r++) {
            int row = part * 32 + r;
            int m = m0 + row;
            float v = stage[row * STAGE_PITCH + col];
            if (m < NN) {
                g_Y[(size_t)m * C + col] = v;
                s += v; q += v * v;
            }
        }
        ((float*)(smp + SM_REDS))[part * 128 + col] = s;
        ((float*)(smp + SM_REDQ))[part * 128 + col] = q;
    }
    __syncthreads();
    if (t < 128) {
        float s = 0.f, q = 0.f;
#pragma unroll
        for (int u = 0; u < 4; u++) {
            s += ((float*)(smp + SM_REDS))[u * 128 + t];
            q += ((float*)(smp + SM_REDQ))[u * 128 + t];
        }
        g_psum[blockIdx.x * C + t] = s;
        g_psq [blockIdx.x * C + t] = q;
    }
}

// ---------------- final layer: [N,896]@[896,36] fp32 ----------------
__global__ __launch_bounds__(256, 2) void final_kernel(
    const int* __restrict__ idx,
    const float* __restrict__ Wl, const float* __restrict__ bl,
    float* __restrict__ out)
{
    const float* __restrict__ Hin = g_Y;
    __shared__ float sA[32 * 132];
    __shared__ float sB[32 * 40];
    __shared__ int   sIdx[128 * 7];
    __shared__ float sSc[128];
    __shared__ float sSh[128];

    const int t  = threadIdx.x;
    const int m0 = blockIdx.x * 128;
    for (int e = t; e < 128 * 7; e += 256) {
        int m = m0 + e / 7;
        sIdx[e] = (m < NN) ? idx[m * 7 + (e - (e / 7) * 7)] : 0;
    }
    if (t < 128) { sSc[t] = g_scale[t]; sSh[t] = g_shift[t]; }
    __syncthreads();

    const int ty = t >> 4, tx = t & 15;
    const int lrow = t >> 3, lk = (t & 7) << 2;
    const bool active = (tx < 12);
    const int cbase = active ? tx * 3 : 0;

    float acc[8][3];
#pragma unroll
    for (int i = 0; i < 8; i++)
#pragma unroll
        for (int jj = 0; jj < 3; jj++) acc[i][jj] = 0.f;

#pragma unroll 1
    for (int kt = 0; kt < 28; kt++) {
        const int j  = kt >> 2;
        const int cc = ((kt & 3) << 5) + lk;
        const float sc0 = sSc[cc], sc1 = sSc[cc + 1], sc2 = sSc[cc + 2], sc3 = sSc[cc + 3];
        const float sh0 = sSh[cc], sh1 = sSh[cc + 1], sh2 = sSh[cc + 2], sh3 = sSh[cc + 3];
#pragma unroll
        for (int p = 0; p < 4; p++) {
            int row = lrow + (p << 5);
            int nb  = sIdx[row * 7 + j];
            float4 v = *reinterpret_cast<const float4*>(&Hin[(size_t)nb * C + cc]);
            sA[(lk + 0) * 132 + row] = fmaxf(fmaf(v.x, sc0, sh0), 0.f);
            sA[(lk + 1) * 132 + row] = fmaxf(fmaf(v.y, sc1, sh1), 0.f);
            sA[(lk + 2) * 132 + row] = fmaxf(fmaf(v.z, sc2, sh2), 0.f);
            sA[(lk + 3) * 132 + row] = fmaxf(fmaf(v.w, sc3, sh3), 0.f);
        }
        for (int e = t; e < 32 * 36; e += 256) {
            int kr = e / 36, nc = e - kr * 36;
            sB[kr * 40 + nc] = Wl[(size_t)(kt * 32 + kr) * 36 + nc];
        }
        __syncthreads();
#pragma unroll 8
        for (int k = 0; k < 32; k++) {
            float4 aA = *reinterpret_cast<const float4*>(&sA[k * 132 + (ty << 3)]);
            float4 aB = *reinterpret_cast<const float4*>(&sA[k * 132 + (ty << 3) + 4]);
            float af[8] = { aA.x, aA.y, aA.z, aA.w, aB.x, aB.y, aB.z, aB.w };
            float b0v = sB[k * 40 + cbase];
            float b1v = sB[k * 40 + cbase + 1];
            float b2v = sB[k * 40 + cbase + 2];
#pragma unroll
            for (int i = 0; i < 8; i++) {
                acc[i][0] = fmaf(af[i], b0v, acc[i][0]);
                acc[i][1] = fmaf(af[i], b1v, acc[i][1]);
                acc[i][2] = fmaf(af[i], b2v, acc[i][2]);
            }
        }
        __syncthreads();
    }

    if (active) {
        float bb0 = bl[cbase], bb1 = bl[cbase + 1], bb2 = bl[cbase + 2];
#pragma unroll
        for (int i = 0; i < 8; i++) {
            int m = m0 + (ty << 3) + i;
            if (m < NN) {
                out[(size_t)m * NCLS + cbase + 0] = acc[i][0] + bb0;
                out[(size_t)m * NCLS + cbase + 1] = acc[i][1] + bb1;
                out[(size_t)m * NCLS + cbase + 2] = acc[i][2] + bb2;
            }
        }
    }
}

// ---------------- launch ----------------
extern "C" void kernel_launch(void* const* d_in, const int* in_sizes, int n_in,
                              void* d_out, int out_size)
{
    const float* x   = (const float*)d_in[0];
    const int*   idx = (const int*)  d_in[1];
    const float* W0  = (const float*)d_in[2];
    const float* b0  = (const float*)d_in[3];
    const float* g0  = (const float*)d_in[4];
    const float* be0 = (const float*)d_in[5];
    const float* Wm  = (const float*)d_in[6];
    const float* bm  = (const float*)d_in[7];
    const float* gm  = (const float*)d_in[8];
    const float* bem = (const float*)d_in[9];
    const float* Wl  = (const float*)d_in[10];
    const float* bl  = (const float*)d_in[11];
    float* out = (float*)d_out;

    static int smem_set = 0;
    if (!smem_set) {
        cudaFuncSetAttribute(gemm_mma, cudaFuncAttributeMaxDynamicSharedMemorySize, GEMM_SMEM);
        smem_set = 1;
    }

    prep_w<<<dim3(28, 4, NLAY), dim3(32, 32)>>>(Wm);
    layer0_kernel<<<NB0, 128>>>(x, idx, W0, b0);
    stats_final<<<1, 1024>>>(NB0, g0, be0);
    convert_kernel<<<(NN * 32 + 255) / 256, 256>>>();

    for (int l = 0; l < NLAY; l++) {
        gemm_mma<<<NBM, 512, GEMM_SMEM>>>(l, idx, bm + (size_t)l * C);
        stats_final<<<1, 1024>>>(NBM, gm + (size_t)l * C, bem + (size_t)l * C);
        if (l < NLAY - 1)
            convert_kernel<<<(NN * 32 + 255) / 256, 256>>>();
    }

    final_kernel<<<NBM, 256>>>(idx, Wl, bl, out);
}